// round 3
// baseline (speedup 1.0000x reference)
#include <cuda_runtime.h>
#include <math.h>

#define B_TOT 512
#define N_TOK 343
#define DIM   96
#define HEADS 3
#define HD    32
#define NW    64
#define NN    (N_TOK * N_TOK)   // 117649

// ---------------- scratch (device globals: no allocation allowed) ----------
__device__ float g_q [(size_t)B_TOT * HEADS * N_TOK * HD];   // [B][H][N][hd], pre-scaled
__device__ float g_k [(size_t)B_TOT * HEADS * N_TOK * HD];
__device__ float g_v [(size_t)B_TOT * HEADS * N_TOK * HD];
__device__ float g_ao[(size_t)B_TOT * N_TOK * DIM];          // [B][N][H*hd]
__device__ float g_cb[(size_t)NW * HEADS * NN];              // combined mask+bias, 90MB

// ---------------- fast exp: FFMA-only, avoids MUFU bottleneck --------------
__device__ __forceinline__ float fast_exp(float x) {
    float y = x * 1.4426950408889634f;        // log2(e)
    y = fmaxf(y, -87.0f);
    float t = y + 12582912.0f;                // round-to-nearest magic (1.5*2^23)
    float f = y - (t - 12582912.0f);          // f in [-0.5, 0.5]
    float p = 1.3333558146428443e-3f;
    p = fmaf(p, f, 9.618129107628477e-3f);
    p = fmaf(p, f, 5.550410866482158e-2f);
    p = fmaf(p, f, 2.402265069591007e-1f);
    p = fmaf(p, f, 6.931471805599453e-1f);
    p = fmaf(p, f, 1.0f);
    return __int_as_float(__float_as_int(p) + (__float_as_int(t) << 23));
}

// ---------------- kernel 0: combined bias table ----------------------------
// g_cb[(w*3+h)][i][j] = mask[w][i][j] + rpb[relidx[i][j]][h]
__global__ __launch_bounds__(352)
void cb_kernel(const float* __restrict__ mask,
               const float* __restrict__ rpb,
               const int*   __restrict__ relidx) {
    const int i  = blockIdx.x;
    const int wh = blockIdx.y;
    const int w  = wh / HEADS;
    const int h  = wh - w * HEADS;
    const int j  = threadIdx.x;
    if (j < N_TOK) {
        int rel = relidx[i * N_TOK + j];
        g_cb[(size_t)wh * NN + i * N_TOK + j] =
            mask[(size_t)w * NN + i * N_TOK + j] + rpb[rel * HEADS + h];
    }
}

// ---------------- kernel 1: QKV GEMM third + bias + scale + relayout -------
// CTA: tile M=64 tokens x N=96 cols (one of q/k/v by blockIdx.y).
// Thread: 8 tokens x 3 cols. Per warp-k: 8 bcast + 3 LDS vs 24 FFMA.
__global__ __launch_bounds__(256, 3)
void qkv_kernel(const float* __restrict__ x,
                const float* __restrict__ w,
                const float* __restrict__ bias) {
    __shared__ float ws[96 * 100];    // [k][cc], pad 100
    __shared__ float xs[64 * 96];     // [t][k]  (broadcast reads: no pad needed)
    __shared__ float bs[96];
    const int tid   = threadIdx.x;
    const int third = blockIdx.y;
    const int m0    = blockIdx.x * 64;

    for (int idx = tid; idx < 96 * 96; idx += 256) {
        int cc = idx / 96, k = idx - cc * 96;
        ws[k * 100 + cc] = w[(third * 96 + cc) * 96 + k];
    }
    if (tid < 96) bs[tid] = bias[third * 96 + tid];
    for (int idx = tid; idx < 64 * 96; idx += 256) {
        xs[idx] = x[(size_t)m0 * 96 + idx];
    }
    __syncthreads();

    const int r = tid >> 5;    // warp: token group (8 tokens)
    const int l = tid & 31;    // lane: cols l, l+32, l+64

    float acc[8][3];
    #pragma unroll
    for (int i = 0; i < 8; i++)
        #pragma unroll
        for (int j = 0; j < 3; j++) acc[i][j] = 0.f;

    const float* xp = xs + r * 8 * 96;
    #pragma unroll 4
    for (int k = 0; k < 96; k++) {
        float wv0 = ws[k * 100 + l];
        float wv1 = ws[k * 100 + l + 32];
        float wv2 = ws[k * 100 + l + 64];
        #pragma unroll
        for (int i = 0; i < 8; i++) {
            float xv = xp[i * 96 + k];
            acc[i][0] = fmaf(xv, wv0, acc[i][0]);
            acc[i][1] = fmaf(xv, wv1, acc[i][1]);
            acc[i][2] = fmaf(xv, wv2, acc[i][2]);
        }
    }

    // epilogue: c = l + 32*j  ->  head hh=j, dim d=l (coalesced 128B stores)
    const float qscale = 0.17677669529663687f;   // 1/sqrt(32)
    #pragma unroll
    for (int i = 0; i < 8; i++) {
        int m = m0 + r * 8 + i;
        int b = m / N_TOK;
        int n = m - b * N_TOK;
        #pragma unroll
        for (int j = 0; j < 3; j++) {
            float val = acc[i][j] + bs[l + 32 * j];
            size_t off = (((size_t)(b * HEADS + j)) * N_TOK + n) * HD + l;
            if (third == 0)      g_q[off] = val * qscale;
            else if (third == 1) g_k[off] = val;
            else                 g_v[off] = val;
        }
    }
}

// ---------------- kernel 2: fused attention per (b, h) ---------------------
__global__ __launch_bounds__(512, 1)
void attn_kernel() {
    extern __shared__ float sm[];
    float* ks = sm;                    // [352][33]   (rows 343..351 zeroed)
    float* vs = sm + 352 * 33;         // [32][356]   V transposed, col 343 zeroed
    float* pb = vs + 32 * 356;         // [64][344]   probs, elem 343 zeroed
    float* qs = pb + 64 * 344;         // [64][32]

    const int b    = blockIdx.x;
    const int h    = blockIdx.y;
    const int tid  = threadIdx.x;
    const int lane = tid & 31;
    const int w    = tid >> 5;         // warp 0..15

    const size_t bh_off = ((size_t)(b * HEADS + h)) * N_TOK * HD;
    const float* kg = g_k + bh_off;
    const float* vg = g_v + bh_off;
    const float* qg = g_q + bh_off;
    const float* cbp = g_cb + (size_t)((b & (NW - 1)) * HEADS + h) * NN;

    for (int idx = tid; idx < N_TOK * HD; idx += 512) {
        int n = idx >> 5, d = idx & 31;
        ks[n * 33 + d] = kg[idx];
        vs[d * 356 + n] = vg[idx];
    }
    for (int idx = tid; idx < 9 * 32; idx += 512) {   // zero pad rows of K
        int n = 343 + (idx >> 5), d = idx & 31;
        ks[n * 33 + d] = 0.f;
    }
    if (tid < 32) vs[tid * 356 + 343] = 0.f;
    if (tid < 64) pb[tid * 344 + 343] = 0.f;
    __syncthreads();

    for (int pass = 0; pass < 6; pass++) {
        const int ibase = pass * 64 + w * 4;

        #pragma unroll
        for (int qi = 0; qi < 4; qi++) {
            int i = ibase + qi;
            qs[(w * 4 + qi) * 32 + lane] = (i < N_TOK) ? qg[i * HD + lane] : 0.f;
        }
        __syncwarp();

        // ---- scores: s[qi][tt] for j = lane + 32*tt ----
        float s[4][11];
        #pragma unroll
        for (int qi = 0; qi < 4; qi++) {
            int i = ibase + qi;
            bool iv = (i < N_TOK);
            #pragma unroll
            for (int tt = 0; tt < 11; tt++) {
                int j = lane + 32 * tt;
                float init = 0.f;
                if (iv && j < N_TOK) init = cbp[i * N_TOK + j];
                s[qi][tt] = init;
            }
        }
        const float* qb = qs + w * 4 * 32;
        for (int d = 0; d < 32; d++) {
            float kv[11];
            #pragma unroll
            for (int tt = 0; tt < 11; tt++)
                kv[tt] = ks[(lane + 32 * tt) * 33 + d];
            #pragma unroll
            for (int qi = 0; qi < 4; qi++) {
                float qv = qb[qi * 32 + d];
                #pragma unroll
                for (int tt = 0; tt < 11; tt++)
                    s[qi][tt] = fmaf(qv, kv[tt], s[qi][tt]);
            }
        }

        // ---- exp + row sums ----
        float inv[4];
        #pragma unroll
        for (int qi = 0; qi < 4; qi++) {
            float sum = 0.f;
            float* prow = pb + (w * 4 + qi) * 344;
            #pragma unroll
            for (int tt = 0; tt < 11; tt++) {
                int j = lane + 32 * tt;
                if (j < N_TOK) {
                    float p = fast_exp(s[qi][tt]);
                    prow[j] = p;
                    sum += p;
                }
            }
            #pragma unroll
            for (int off = 16; off > 0; off >>= 1)
                sum += __shfl_xor_sync(0xffffffffu, sum, off);
            inv[qi] = 1.0f / sum;
        }
        __syncwarp();

        // ---- AV: lane owns output dim d = lane ----
        float acc0 = 0.f, acc1 = 0.f, acc2 = 0.f, acc3 = 0.f;
        const float4* vrow  = (const float4*)(vs + lane * 356);
        const float4* prow0 = (const float4*)(pb + (w * 4 + 0) * 344);
        const float4* prow1 = (const float4*)(pb + (w * 4 + 1) * 344);
        const float4* prow2 = (const float4*)(pb + (w * 4 + 2) * 344);
        const float4* prow3 = (const float4*)(pb + (w * 4 + 3) * 344);
        for (int jq = 0; jq < 86; jq++) {
            float4 vv = vrow[jq];
            float4 p0 = prow0[jq];
            acc0 = fmaf(p0.x, vv.x, acc0); acc0 = fmaf(p0.y, vv.y, acc0);
            acc0 = fmaf(p0.z, vv.z, acc0); acc0 = fmaf(p0.w, vv.w, acc0);
            float4 p1 = prow1[jq];
            acc1 = fmaf(p1.x, vv.x, acc1); acc1 = fmaf(p1.y, vv.y, acc1);
            acc1 = fmaf(p1.z, vv.z, acc1); acc1 = fmaf(p1.w, vv.w, acc1);
            float4 p2 = prow2[jq];
            acc2 = fmaf(p2.x, vv.x, acc2); acc2 = fmaf(p2.y, vv.y, acc2);
            acc2 = fmaf(p2.z, vv.z, acc2); acc2 = fmaf(p2.w, vv.w, acc2);
            float4 p3 = prow3[jq];
            acc3 = fmaf(p3.x, vv.x, acc3); acc3 = fmaf(p3.y, vv.y, acc3);
            acc3 = fmaf(p3.z, vv.z, acc3); acc3 = fmaf(p3.w, vv.w, acc3);
        }
        float accs[4] = {acc0, acc1, acc2, acc3};
        #pragma unroll
        for (int qi = 0; qi < 4; qi++) {
            int i = ibase + qi;
            if (i < N_TOK)
                g_ao[((size_t)b * N_TOK + i) * DIM + h * HD + lane] = accs[qi] * inv[qi];
        }
        __syncwarp();
    }
}

// ---------------- kernel 3: output projection ------------------------------
// g_ao[175616, 96] @ proj_w^T[96, 96] + proj_b -> out. Same tiling as qkv.
__global__ __launch_bounds__(256, 3)
void proj_kernel(const float* __restrict__ w,
                 const float* __restrict__ bias,
                 float* __restrict__ out) {
    __shared__ float ws[96 * 100];
    __shared__ float xs[64 * 96];
    __shared__ float bs[96];
    const int tid = threadIdx.x;
    const int m0  = blockIdx.x * 64;

    for (int idx = tid; idx < 96 * 96; idx += 256) {
        int cc = idx / 96, k = idx - cc * 96;
        ws[k * 100 + cc] = w[cc * 96 + k];
    }
    if (tid < 96) bs[tid] = bias[tid];
    for (int idx = tid; idx < 64 * 96; idx += 256) {
        xs[idx] = g_ao[(size_t)m0 * 96 + idx];
    }
    __syncthreads();

    const int r = tid >> 5;
    const int l = tid & 31;

    float acc[8][3];
    #pragma unroll
    for (int i = 0; i < 8; i++)
        #pragma unroll
        for (int j = 0; j < 3; j++) acc[i][j] = 0.f;

    const float* xp = xs + r * 8 * 96;
    #pragma unroll 4
    for (int k = 0; k < 96; k++) {
        float wv0 = ws[k * 100 + l];
        float wv1 = ws[k * 100 + l + 32];
        float wv2 = ws[k * 100 + l + 64];
        #pragma unroll
        for (int i = 0; i < 8; i++) {
            float xv = xp[i * 96 + k];
            acc[i][0] = fmaf(xv, wv0, acc[i][0]);
            acc[i][1] = fmaf(xv, wv1, acc[i][1]);
            acc[i][2] = fmaf(xv, wv2, acc[i][2]);
        }
    }

    #pragma unroll
    for (int i = 0; i < 8; i++) {
        size_t m = m0 + r * 8 + i;
        #pragma unroll
        for (int j = 0; j < 3; j++) {
            out[m * 96 + l + 32 * j] = acc[i][j] + bs[l + 32 * j];
        }
    }
}

// ---------------- launch ---------------------------------------------------
extern "C" void kernel_launch(void* const* d_in, const int* in_sizes, int n_in,
                              void* d_out, int out_size) {
    const float* x      = (const float*)d_in[0];
    const float* mask   = (const float*)d_in[1];
    const float* qkv_w  = (const float*)d_in[2];
    const float* qkv_b  = (const float*)d_in[3];
    const float* proj_w = (const float*)d_in[4];
    const float* proj_b = (const float*)d_in[5];
    const float* rpb    = (const float*)d_in[6];
    const int*   relidx = (const int*)d_in[7];
    float* out = (float*)d_out;

    const int smem_attn = (352 * 33 + 32 * 356 + 64 * 344 + 64 * 32) * 4;  // 188,288 B
    cudaFuncSetAttribute(attn_kernel, cudaFuncAttributeMaxDynamicSharedMemorySize, smem_attn);

    cb_kernel  <<<dim3(N_TOK, NW * HEADS), 352>>>(mask, rpb, relidx);
    qkv_kernel <<<dim3(2744, 3), 256>>>(x, qkv_w, qkv_b);
    attn_kernel<<<dim3(512, 3), 512, smem_attn>>>();
    proj_kernel<<<2744, 256>>>(proj_w, proj_b, out);
    (void)in_sizes; (void)n_in; (void)out_size;
}

// round 4
// speedup vs baseline: 1.6797x; 1.6797x over previous
#include <cuda_runtime.h>
#include <math.h>

#define B_TOT 512
#define N_TOK 343
#define DIM   96
#define HEADS 3
#define HD    32
#define NW    64
#define CB_STRIDE 344
#define CB_SLICE  (N_TOK * CB_STRIDE)   // 117992

// ---------------- scratch (device globals: no allocation allowed) ----------
__device__ float g_q [(size_t)B_TOT * HEADS * N_TOK * HD];   // [B][H][N][hd], pre-scaled
__device__ float g_k [(size_t)B_TOT * HEADS * N_TOK * HD];
__device__ float g_v [(size_t)B_TOT * HEADS * N_TOK * HD];
__device__ float g_ao[(size_t)B_TOT * N_TOK * DIM];          // [B][N][H*hd]
__device__ float g_cb[(size_t)NW * HEADS * CB_SLICE + 64];   // mask+bias, stride-344 rows

// ---------------- helpers --------------------------------------------------
__device__ __forceinline__ float fast_exp(float x) {
    float y = x * 1.4426950408889634f;        // log2(e)
    y = fmaxf(y, -87.0f);
    float t = y + 12582912.0f;                // round-to-nearest magic (1.5*2^23)
    float f = y - (t - 12582912.0f);          // f in [-0.5, 0.5]
    float p = 1.3333558146428443e-3f;
    p = fmaf(p, f, 9.618129107628477e-3f);
    p = fmaf(p, f, 5.550410866482158e-2f);
    p = fmaf(p, f, 2.402265069591007e-1f);
    p = fmaf(p, f, 6.931471805599453e-1f);
    p = fmaf(p, f, 1.0f);
    return __int_as_float(__float_as_int(p) + (__float_as_int(t) << 23));
}

__device__ __forceinline__ unsigned f2tf(float x) {
    unsigned r;
    asm("cvt.rna.tf32.f32 %0, %1;" : "=r"(r) : "f"(x));
    return r;
}

__device__ __forceinline__ void mma_tf32(float& c0, float& c1, float& c2, float& c3,
                                         unsigned a0, unsigned a1, unsigned a2, unsigned a3,
                                         unsigned b0, unsigned b1) {
    asm volatile("mma.sync.aligned.m16n8k8.row.col.f32.tf32.tf32.f32 "
                 "{%0,%1,%2,%3}, {%4,%5,%6,%7}, {%8,%9}, {%0,%1,%2,%3};"
                 : "+f"(c0), "+f"(c1), "+f"(c2), "+f"(c3)
                 : "r"(a0), "r"(a1), "r"(a2), "r"(a3), "r"(b0), "r"(b1));
}

// ---------------- kernel 0: combined bias table (stride 344) ---------------
__global__ __launch_bounds__(352)
void cb_kernel(const float* __restrict__ mask,
               const float* __restrict__ rpb,
               const int*   __restrict__ relidx) {
    const int i  = blockIdx.x;
    const int wh = blockIdx.y;
    const int w  = wh / HEADS;
    const int h  = wh - w * HEADS;
    const int j  = threadIdx.x;
    if (j < N_TOK) {
        int rel = relidx[i * N_TOK + j];
        g_cb[(size_t)wh * CB_SLICE + i * CB_STRIDE + j] =
            mask[(size_t)w * N_TOK * N_TOK + i * N_TOK + j] + rpb[rel * HEADS + h];
    }
}

// ---------------- kernel 1: QKV GEMM third + bias + scale + relayout -------
__global__ __launch_bounds__(256, 3)
void qkv_kernel(const float* __restrict__ x,
                const float* __restrict__ w,
                const float* __restrict__ bias) {
    __shared__ float ws[96 * 100];
    __shared__ float xs[64 * 96];
    __shared__ float bs[96];
    const int tid   = threadIdx.x;
    const int third = blockIdx.y;
    const int m0    = blockIdx.x * 64;

    for (int idx = tid; idx < 96 * 96; idx += 256) {
        int cc = idx / 96, k = idx - cc * 96;
        ws[k * 100 + cc] = w[(third * 96 + cc) * 96 + k];
    }
    if (tid < 96) bs[tid] = bias[third * 96 + tid];
    for (int idx = tid; idx < 64 * 96; idx += 256)
        xs[idx] = x[(size_t)m0 * 96 + idx];
    __syncthreads();

    const int r = tid >> 5;
    const int l = tid & 31;

    float acc[8][3];
    #pragma unroll
    for (int i = 0; i < 8; i++)
        #pragma unroll
        for (int j = 0; j < 3; j++) acc[i][j] = 0.f;

    const float* xp = xs + r * 8 * 96;
    #pragma unroll 4
    for (int k = 0; k < 96; k++) {
        float wv0 = ws[k * 100 + l];
        float wv1 = ws[k * 100 + l + 32];
        float wv2 = ws[k * 100 + l + 64];
        #pragma unroll
        for (int i = 0; i < 8; i++) {
            float xv = xp[i * 96 + k];
            acc[i][0] = fmaf(xv, wv0, acc[i][0]);
            acc[i][1] = fmaf(xv, wv1, acc[i][1]);
            acc[i][2] = fmaf(xv, wv2, acc[i][2]);
        }
    }

    const float qscale = 0.17677669529663687f;
    #pragma unroll
    for (int i = 0; i < 8; i++) {
        int m = m0 + r * 8 + i;
        int b = m / N_TOK;
        int n = m - b * N_TOK;
        #pragma unroll
        for (int j = 0; j < 3; j++) {
            float val = acc[i][j] + bs[l + 32 * j];
            size_t off = (((size_t)(b * HEADS + j)) * N_TOK + n) * HD + l;
            if (third == 0)      g_q[off] = val * qscale;
            else if (third == 1) g_k[off] = val;
            else                 g_v[off] = val;
        }
    }
}

// ---------------- kernel 2: fused attention, tf32 mma.sync -----------------
// 22 warps; warp w owns query stripe rows [16w, 16w+16). K/V pre-arranged in
// B-fragment order in smem (conflict-free LDS.64). No block barriers in loop.
__global__ __launch_bounds__(704, 1)
void attn_kernel() {
    extern __shared__ unsigned smu[];
    unsigned* kfrag = smu;               // [43*4][64]  : 11008
    unsigned* vfrag = smu + 11008;       // [43*4][64]  : 11008
    unsigned* pwarp = smu + 22016;       // [22][16][68]: 23936

    const int b    = blockIdx.x;
    const int h    = blockIdx.y;
    const int tid  = threadIdx.x;
    const int lane = tid & 31;
    const int w    = tid >> 5;           // 0..21
    const int g    = lane >> 2;          // 0..7
    const int tig  = lane & 3;           // 0..3

    const size_t bh_off = ((size_t)(b * HEADS + h)) * N_TOK * HD;
    const float* kg = g_k + bh_off;
    const float* vg = g_v + bh_off;
    const float* qg = g_q + bh_off;
    const float* cbp = g_cb + (size_t)((b & (NW - 1)) * HEADS + h) * CB_SLICE;

    // ---- build K B-fragments: kfrag[(nt*4+kk)*64 + l*2 + {0,1}] ----
    //   val0 = K[nt*8+gl][kk*8+tl], val1 = K[nt*8+gl][kk*8+tl+4]
    for (int idx = tid; idx < 43 * 4 * 32; idx += 704) {
        int tile = idx >> 5, l = idx & 31;
        int nt = tile >> 2, kk = tile & 3;
        int gl = l >> 2, tl = l & 3;
        int n = nt * 8 + gl;
        int d0 = kk * 8 + tl;
        float v0 = (n < N_TOK) ? kg[n * 32 + d0]     : 0.f;
        float v1 = (n < N_TOK) ? kg[n * 32 + d0 + 4] : 0.f;
        kfrag[tile * 64 + l * 2]     = f2tf(v0);
        kfrag[tile * 64 + l * 2 + 1] = f2tf(v1);
    }
    // ---- build V B-fragments: vfrag[(kt*4+nn)*64 + l*2 + {0,1}] ----
    //   val0 = V[kt*8+tl][nn*8+gl], val1 = V[kt*8+tl+4][nn*8+gl]
    for (int idx = tid; idx < 43 * 4 * 32; idx += 704) {
        int tile = idx >> 5, l = idx & 31;
        int kt = tile >> 2, nn = tile & 3;
        int gl = l >> 2, tl = l & 3;
        int k0 = kt * 8;
        float v0 = (k0 + tl     < N_TOK) ? vg[(k0 + tl)     * 32 + nn * 8 + gl] : 0.f;
        float v1 = (k0 + tl + 4 < N_TOK) ? vg[(k0 + tl + 4) * 32 + nn * 8 + gl] : 0.f;
        vfrag[tile * 64 + l * 2]     = f2tf(v0);
        vfrag[tile * 64 + l * 2 + 1] = f2tf(v1);
    }
    __syncthreads();

    // ---- per-warp stripe ----
    const int i0 = w * 16;
    const int iA = i0 + g, iB = i0 + g + 8;
    const bool vA = (iA < N_TOK), vB = (iB < N_TOK);

    // Q A-fragments for all 4 k-steps
    unsigned qa[4][4];
    #pragma unroll
    for (int kk = 0; kk < 4; kk++) {
        int d0 = kk * 8 + tig;
        qa[kk][0] = vA ? f2tf(qg[iA * 32 + d0])     : 0u;
        qa[kk][1] = vB ? f2tf(qg[iB * 32 + d0])     : 0u;
        qa[kk][2] = vA ? f2tf(qg[iA * 32 + d0 + 4]) : 0u;
        qa[kk][3] = vB ? f2tf(qg[iB * 32 + d0 + 4]) : 0u;
    }

    float av[4][4];
    #pragma unroll
    for (int nn = 0; nn < 4; nn++)
        #pragma unroll
        for (int e = 0; e < 4; e++) av[nn][e] = 0.f;

    float sumA = 0.f, sumB = 0.f;
    const float* cbA = cbp + (size_t)iA * CB_STRIDE;
    const float* cbB = cbp + (size_t)iB * CB_STRIDE;
    unsigned* pw = pwarp + w * (16 * 68);

    for (int chunk = 0; chunk < 6; chunk++) {
        const int n0  = chunk * 64;
        const int ntc = (chunk < 5) ? 8 : 3;

        // ---- QK scores + bias + exp -> P (tf32) in pwarp ----
        for (int nt = 0; nt < ntc; nt++) {
            const int ntg = chunk * 8 + nt;
            const int j0  = n0 + nt * 8 + 2 * tig;

            float cb00, cb01, cb10, cb11;
            if (vA && j0 < N_TOK) {
                float2 t = *(const float2*)(cbA + j0);
                cb00 = t.x; cb01 = t.y;
            } else { cb00 = cb01 = -1e30f; }
            if (vB && j0 < N_TOK) {
                float2 t = *(const float2*)(cbB + j0);
                cb10 = t.x; cb11 = t.y;
            } else { cb10 = cb11 = -1e30f; }
            if (j0 + 1 >= N_TOK) { cb01 = -1e30f; cb11 = -1e30f; }

            float c0 = 0.f, c1 = 0.f, c2 = 0.f, c3 = 0.f;
            #pragma unroll
            for (int kk = 0; kk < 4; kk++) {
                uint2 bb = *(const uint2*)(kfrag + (ntg * 4 + kk) * 64 + lane * 2);
                mma_tf32(c0, c1, c2, c3, qa[kk][0], qa[kk][1], qa[kk][2], qa[kk][3],
                         bb.x, bb.y);
            }

            float p0 = fast_exp(c0 + cb00);
            float p1 = fast_exp(c1 + cb01);
            float p2 = fast_exp(c2 + cb10);
            float p3 = fast_exp(c3 + cb11);
            sumA += p0 + p1;
            sumB += p2 + p3;

            const int colc = nt * 8 + 2 * tig;
            uint2 sA = make_uint2(f2tf(p0), f2tf(p1));
            uint2 sB = make_uint2(f2tf(p2), f2tf(p3));
            *(uint2*)(pw + g * 68 + colc)       = sA;
            *(uint2*)(pw + (g + 8) * 68 + colc) = sB;
        }
        __syncwarp();

        // ---- AV partial: av += P_chunk @ V_chunk ----
        for (int kk2 = 0; kk2 < ntc; kk2++) {
            unsigned a0 = pw[g * 68 + kk2 * 8 + tig];
            unsigned a1 = pw[(g + 8) * 68 + kk2 * 8 + tig];
            unsigned a2 = pw[g * 68 + kk2 * 8 + tig + 4];
            unsigned a3 = pw[(g + 8) * 68 + kk2 * 8 + tig + 4];
            const int ktg = chunk * 8 + kk2;
            #pragma unroll
            for (int nn = 0; nn < 4; nn++) {
                uint2 bb = *(const uint2*)(vfrag + (ktg * 4 + nn) * 64 + lane * 2);
                mma_tf32(av[nn][0], av[nn][1], av[nn][2], av[nn][3],
                         a0, a1, a2, a3, bb.x, bb.y);
            }
        }
        __syncwarp();
    }

    // ---- rowsum reduce within quad (lanes sharing g) ----
    sumA += __shfl_xor_sync(0xffffffffu, sumA, 1);
    sumA += __shfl_xor_sync(0xffffffffu, sumA, 2);
    sumB += __shfl_xor_sync(0xffffffffu, sumB, 1);
    sumB += __shfl_xor_sync(0xffffffffu, sumB, 2);
    const float invA = 1.0f / sumA;
    const float invB = 1.0f / sumB;

    // ---- store normalized output ----
    #pragma unroll
    for (int nn = 0; nn < 4; nn++) {
        const int d = nn * 8 + 2 * tig;
        if (vA) {
            float2 o = make_float2(av[nn][0] * invA, av[nn][1] * invA);
            *(float2*)(g_ao + ((size_t)b * N_TOK + iA) * DIM + h * HD + d) = o;
        }
        if (vB) {
            float2 o = make_float2(av[nn][2] * invB, av[nn][3] * invB);
            *(float2*)(g_ao + ((size_t)b * N_TOK + iB) * DIM + h * HD + d) = o;
        }
    }
}

// ---------------- kernel 3: output projection ------------------------------
__global__ __launch_bounds__(256, 3)
void proj_kernel(const float* __restrict__ w,
                 const float* __restrict__ bias,
                 float* __restrict__ out) {
    __shared__ float ws[96 * 100];
    __shared__ float xs[64 * 96];
    __shared__ float bs[96];
    const int tid = threadIdx.x;
    const int m0  = blockIdx.x * 64;

    for (int idx = tid; idx < 96 * 96; idx += 256) {
        int cc = idx / 96, k = idx - cc * 96;
        ws[k * 100 + cc] = w[cc * 96 + k];
    }
    if (tid < 96) bs[tid] = bias[tid];
    for (int idx = tid; idx < 64 * 96; idx += 256)
        xs[idx] = g_ao[(size_t)m0 * 96 + idx];
    __syncthreads();

    const int r = tid >> 5;
    const int l = tid & 31;

    float acc[8][3];
    #pragma unroll
    for (int i = 0; i < 8; i++)
        #pragma unroll
        for (int j = 0; j < 3; j++) acc[i][j] = 0.f;

    const float* xp = xs + r * 8 * 96;
    #pragma unroll 4
    for (int k = 0; k < 96; k++) {
        float wv0 = ws[k * 100 + l];
        float wv1 = ws[k * 100 + l + 32];
        float wv2 = ws[k * 100 + l + 64];
        #pragma unroll
        for (int i = 0; i < 8; i++) {
            float xv = xp[i * 96 + k];
            acc[i][0] = fmaf(xv, wv0, acc[i][0]);
            acc[i][1] = fmaf(xv, wv1, acc[i][1]);
            acc[i][2] = fmaf(xv, wv2, acc[i][2]);
        }
    }

    #pragma unroll
    for (int i = 0; i < 8; i++) {
        size_t m = m0 + r * 8 + i;
        #pragma unroll
        for (int j = 0; j < 3; j++)
            out[m * 96 + l + 32 * j] = acc[i][j] + bs[l + 32 * j];
    }
}

// ---------------- launch ---------------------------------------------------
extern "C" void kernel_launch(void* const* d_in, const int* in_sizes, int n_in,
                              void* d_out, int out_size) {
    const float* x      = (const float*)d_in[0];
    const float* mask   = (const float*)d_in[1];
    const float* qkv_w  = (const float*)d_in[2];
    const float* qkv_b  = (const float*)d_in[3];
    const float* proj_w = (const float*)d_in[4];
    const float* proj_b = (const float*)d_in[5];
    const float* rpb    = (const float*)d_in[6];
    const int*   relidx = (const int*)d_in[7];
    float* out = (float*)d_out;

    const int smem_attn = (11008 + 11008 + 22 * 16 * 68) * 4;   // 183,808 B
    cudaFuncSetAttribute(attn_kernel, cudaFuncAttributeMaxDynamicSharedMemorySize, smem_attn);

    cb_kernel  <<<dim3(N_TOK, NW * HEADS), 352>>>(mask, rpb, relidx);
    qkv_kernel <<<dim3(2744, 3), 256>>>(x, qkv_w, qkv_b);
    attn_kernel<<<dim3(512, 3), 704, smem_attn>>>();
    proj_kernel<<<2744, 256>>>(proj_w, proj_b, out);
    (void)in_sizes; (void)n_in; (void)out_size;
}

// round 5
// speedup vs baseline: 1.9439x; 1.1573x over previous
#include <cuda_runtime.h>
#include <math.h>

#define B_TOT 512
#define N_TOK 343
#define DIM   96
#define HEADS 3
#define HD    32
#define NW    64
#define CB_STRIDE 344
#define CB_SLICE  (N_TOK * CB_STRIDE)   // 117992

// ---------------- scratch (device globals: no allocation allowed) ----------
__device__ float g_q [(size_t)B_TOT * HEADS * N_TOK * HD];   // [B][H][N][hd], pre-scaled
__device__ float g_k [(size_t)B_TOT * HEADS * N_TOK * HD];
__device__ float g_v [(size_t)B_TOT * HEADS * N_TOK * HD];
__device__ float g_ao[(size_t)B_TOT * N_TOK * DIM];          // [B][N][H*hd]
__device__ float g_cb[(size_t)NW * HEADS * CB_SLICE + 64];   // mask+bias, stride-344 rows

// ---------------- helpers --------------------------------------------------
__device__ __forceinline__ float fast_exp(float x) {
    float y = x * 1.4426950408889634f;        // log2(e)
    y = fmaxf(y, -87.0f);
    float t = y + 12582912.0f;                // round-to-nearest magic (1.5*2^23)
    float f = y - (t - 12582912.0f);          // f in [-0.5, 0.5]
    float p = 1.3333558146428443e-3f;
    p = fmaf(p, f, 9.618129107628477e-3f);
    p = fmaf(p, f, 5.550410866482158e-2f);
    p = fmaf(p, f, 2.402265069591007e-1f);
    p = fmaf(p, f, 6.931471805599453e-1f);
    p = fmaf(p, f, 1.0f);
    return __int_as_float(__float_as_int(p) + (__float_as_int(t) << 23));
}

__device__ __forceinline__ unsigned f2tf(float x) {
    unsigned r;
    asm("cvt.rna.tf32.f32 %0, %1;" : "=r"(r) : "f"(x));
    return r;
}

__device__ __forceinline__ void mma_tf32(float& c0, float& c1, float& c2, float& c3,
                                         unsigned a0, unsigned a1, unsigned a2, unsigned a3,
                                         unsigned b0, unsigned b1) {
    asm volatile("mma.sync.aligned.m16n8k8.row.col.f32.tf32.tf32.f32 "
                 "{%0,%1,%2,%3}, {%4,%5,%6,%7}, {%8,%9}, {%0,%1,%2,%3};"
                 : "+f"(c0), "+f"(c1), "+f"(c2), "+f"(c3)
                 : "r"(a0), "r"(a1), "r"(a2), "r"(a3), "r"(b0), "r"(b1));
}

// ---------------- kernel 0: combined bias table (stride 344) ---------------
__global__ __launch_bounds__(352)
void cb_kernel(const float* __restrict__ mask,
               const float* __restrict__ rpb,
               const int*   __restrict__ relidx) {
    const int i  = blockIdx.x;
    const int wh = blockIdx.y;
    const int w  = wh / HEADS;
    const int h  = wh - w * HEADS;
    const int j  = threadIdx.x;
    if (j < N_TOK) {
        int rel = relidx[i * N_TOK + j];
        g_cb[(size_t)wh * CB_SLICE + i * CB_STRIDE + j] =
            mask[(size_t)w * N_TOK * N_TOK + i * N_TOK + j] + rpb[rel * HEADS + h];
    }
}

// ---------------- kernel 1: QKV GEMM third via tf32 mma --------------------
// CTA: 128 tokens x 96 cols (one of q/k/v by blockIdx.y). 8 warps, warp owns
// m16 stripe. W in B-fragment smem; X row-major stride 100 (conflict-free
// A-frag LDS: (100g+tig) mod 32 = 4g+tig, distinct per lane).
__global__ __launch_bounds__(256, 2)
void qkv_kernel(const float* __restrict__ x,
                const float* __restrict__ w,
                const float* __restrict__ bias) {
    extern __shared__ float smf[];
    float*    xs    = smf;                       // [128][100]  51200B
    unsigned* wfrag = (unsigned*)(smf + 12800);  // [12*12][64] 36864B
    float*    bs    = smf + 12800 + 9216;        // [96]
    const int tid   = threadIdx.x;
    const int third = blockIdx.y;
    const int m0    = blockIdx.x * 128;

    // W B-frags: wfrag[(nt*12+kk)*64 + l*2 + {0,1}] = W[c][k], W[c][k+4]
    for (int idx = tid; idx < 12 * 12 * 32; idx += 256) {
        int t = idx >> 5, l = idx & 31;
        int nt = t / 12, kk = t - nt * 12;
        int gl = l >> 2, tl = l & 3;
        int c  = third * 96 + nt * 8 + gl;
        int k0 = kk * 8 + tl;
        wfrag[t * 64 + l * 2]     = f2tf(w[c * 96 + k0]);
        wfrag[t * 64 + l * 2 + 1] = f2tf(w[c * 96 + k0 + 4]);
    }
    if (tid < 96) bs[tid] = bias[third * 96 + tid];
    for (int idx = tid; idx < 128 * 96; idx += 256) {
        int r = idx / 96, c = idx - r * 96;
        xs[r * 100 + c] = x[(size_t)m0 * 96 + idx];
    }
    __syncthreads();

    const int wp   = tid >> 5;
    const int lane = tid & 31;
    const int g    = lane >> 2;
    const int tig  = lane & 3;

    float acc[12][4];
    #pragma unroll
    for (int nt = 0; nt < 12; nt++)
        #pragma unroll
        for (int e = 0; e < 4; e++) acc[nt][e] = 0.f;

    const float* xrA = xs + (wp * 16 + g) * 100;
    const float* xrB = xrA + 8 * 100;
    #pragma unroll
    for (int kk = 0; kk < 12; kk++) {
        unsigned a0 = f2tf(xrA[kk * 8 + tig]);
        unsigned a1 = f2tf(xrB[kk * 8 + tig]);
        unsigned a2 = f2tf(xrA[kk * 8 + tig + 4]);
        unsigned a3 = f2tf(xrB[kk * 8 + tig + 4]);
        #pragma unroll
        for (int nt = 0; nt < 12; nt++) {
            uint2 bb = *(const uint2*)(wfrag + (nt * 12 + kk) * 64 + lane * 2);
            mma_tf32(acc[nt][0], acc[nt][1], acc[nt][2], acc[nt][3],
                     a0, a1, a2, a3, bb.x, bb.y);
        }
    }

    // epilogue: rows mA, mB; cols nt*8 + 2*tig + {0,1}
    const float qscale = 0.17677669529663687f;
    const int mA = m0 + wp * 16 + g;
    const int mB = mA + 8;
    const int bA = mA / N_TOK, nA = mA - bA * N_TOK;
    const int bB = mB / N_TOK, nB = mB - bB * N_TOK;
    #pragma unroll
    for (int nt = 0; nt < 12; nt++) {
        int c0 = nt * 8 + 2 * tig;
        int hh = c0 >> 5, d = c0 & 31;
        float bb0 = bs[c0], bb1 = bs[c0 + 1];
        float2 vA = make_float2(acc[nt][0] + bb0, acc[nt][1] + bb1);
        float2 vB = make_float2(acc[nt][2] + bb0, acc[nt][3] + bb1);
        size_t offA = (((size_t)(bA * HEADS + hh)) * N_TOK + nA) * HD + d;
        size_t offB = (((size_t)(bB * HEADS + hh)) * N_TOK + nB) * HD + d;
        if (third == 0) {
            vA.x *= qscale; vA.y *= qscale; vB.x *= qscale; vB.y *= qscale;
            *(float2*)(g_q + offA) = vA; *(float2*)(g_q + offB) = vB;
        } else if (third == 1) {
            *(float2*)(g_k + offA) = vA; *(float2*)(g_k + offB) = vB;
        } else {
            *(float2*)(g_v + offA) = vA; *(float2*)(g_v + offB) = vB;
        }
    }
}

// ---------------- kernel 2: fused attention, tf32 mma.sync -----------------
// Grid linearized so the 8 CTAs sharing one cb slice are launch-adjacent
// (same wave -> L2 serves 7/8 of the 722MB cb stream).
__global__ __launch_bounds__(704, 1)
void attn_kernel() {
    extern __shared__ unsigned smu[];
    unsigned* kfrag = smu;               // [43*4][64]  : 11008
    unsigned* vfrag = smu + 11008;       // [43*4][64]  : 11008
    unsigned* pwarp = smu + 22016;       // [22][16][68]: 23936

    const int bid  = blockIdx.x;
    const int wh   = bid >> 3;                 // window*3 + h
    const int rep  = bid & 7;
    const int win  = wh / HEADS;
    const int h    = wh - win * HEADS;
    const int b    = rep * NW + win;
    const int tid  = threadIdx.x;
    const int lane = tid & 31;
    const int w    = tid >> 5;           // 0..21
    const int g    = lane >> 2;          // 0..7
    const int tig  = lane & 3;           // 0..3

    const size_t bh_off = ((size_t)(b * HEADS + h)) * N_TOK * HD;
    const float* kg = g_k + bh_off;
    const float* vg = g_v + bh_off;
    const float* qg = g_q + bh_off;
    const float* cbp = g_cb + (size_t)wh * CB_SLICE;

    // ---- build K B-fragments ----
    for (int idx = tid; idx < 43 * 4 * 32; idx += 704) {
        int tile = idx >> 5, l = idx & 31;
        int nt = tile >> 2, kk = tile & 3;
        int gl = l >> 2, tl = l & 3;
        int n = nt * 8 + gl;
        int d0 = kk * 8 + tl;
        float v0 = (n < N_TOK) ? kg[n * 32 + d0]     : 0.f;
        float v1 = (n < N_TOK) ? kg[n * 32 + d0 + 4] : 0.f;
        kfrag[tile * 64 + l * 2]     = f2tf(v0);
        kfrag[tile * 64 + l * 2 + 1] = f2tf(v1);
    }
    // ---- build V B-fragments ----
    for (int idx = tid; idx < 43 * 4 * 32; idx += 704) {
        int tile = idx >> 5, l = idx & 31;
        int kt = tile >> 2, nn = tile & 3;
        int gl = l >> 2, tl = l & 3;
        int k0 = kt * 8;
        float v0 = (k0 + tl     < N_TOK) ? vg[(k0 + tl)     * 32 + nn * 8 + gl] : 0.f;
        float v1 = (k0 + tl + 4 < N_TOK) ? vg[(k0 + tl + 4) * 32 + nn * 8 + gl] : 0.f;
        vfrag[tile * 64 + l * 2]     = f2tf(v0);
        vfrag[tile * 64 + l * 2 + 1] = f2tf(v1);
    }
    __syncthreads();

    const int i0 = w * 16;
    const int iA = i0 + g, iB = i0 + g + 8;
    const bool vA = (iA < N_TOK), vB = (iB < N_TOK);

    unsigned qa[4][4];
    #pragma unroll
    for (int kk = 0; kk < 4; kk++) {
        int d0 = kk * 8 + tig;
        qa[kk][0] = vA ? f2tf(qg[iA * 32 + d0])     : 0u;
        qa[kk][1] = vB ? f2tf(qg[iB * 32 + d0])     : 0u;
        qa[kk][2] = vA ? f2tf(qg[iA * 32 + d0 + 4]) : 0u;
        qa[kk][3] = vB ? f2tf(qg[iB * 32 + d0 + 4]) : 0u;
    }

    float av[4][4];
    #pragma unroll
    for (int nn = 0; nn < 4; nn++)
        #pragma unroll
        for (int e = 0; e < 4; e++) av[nn][e] = 0.f;

    float sumA = 0.f, sumB = 0.f;
    const float* cbA = cbp + (size_t)iA * CB_STRIDE;
    const float* cbB = cbp + (size_t)iB * CB_STRIDE;
    unsigned* pw = pwarp + w * (16 * 68);

    for (int chunk = 0; chunk < 6; chunk++) {
        const int n0  = chunk * 64;
        const int ntc = (chunk < 5) ? 8 : 3;

        for (int nt = 0; nt < ntc; nt++) {
            const int ntg = chunk * 8 + nt;
            const int j0  = n0 + nt * 8 + 2 * tig;

            float cb00, cb01, cb10, cb11;
            if (vA && j0 < N_TOK) {
                float2 t = *(const float2*)(cbA + j0);
                cb00 = t.x; cb01 = t.y;
            } else { cb00 = cb01 = -1e30f; }
            if (vB && j0 < N_TOK) {
                float2 t = *(const float2*)(cbB + j0);
                cb10 = t.x; cb11 = t.y;
            } else { cb10 = cb11 = -1e30f; }
            if (j0 + 1 >= N_TOK) { cb01 = -1e30f; cb11 = -1e30f; }

            float c0 = 0.f, c1 = 0.f, c2 = 0.f, c3 = 0.f;
            #pragma unroll
            for (int kk = 0; kk < 4; kk++) {
                uint2 bb = *(const uint2*)(kfrag + (ntg * 4 + kk) * 64 + lane * 2);
                mma_tf32(c0, c1, c2, c3, qa[kk][0], qa[kk][1], qa[kk][2], qa[kk][3],
                         bb.x, bb.y);
            }

            float p0 = fast_exp(c0 + cb00);
            float p1 = fast_exp(c1 + cb01);
            float p2 = fast_exp(c2 + cb10);
            float p3 = fast_exp(c3 + cb11);
            sumA += p0 + p1;
            sumB += p2 + p3;

            const int colc = nt * 8 + 2 * tig;
            uint2 sA = make_uint2(f2tf(p0), f2tf(p1));
            uint2 sB = make_uint2(f2tf(p2), f2tf(p3));
            *(uint2*)(pw + g * 68 + colc)       = sA;
            *(uint2*)(pw + (g + 8) * 68 + colc) = sB;
        }
        __syncwarp();

        for (int kk2 = 0; kk2 < ntc; kk2++) {
            unsigned a0 = pw[g * 68 + kk2 * 8 + tig];
            unsigned a1 = pw[(g + 8) * 68 + kk2 * 8 + tig];
            unsigned a2 = pw[g * 68 + kk2 * 8 + tig + 4];
            unsigned a3 = pw[(g + 8) * 68 + kk2 * 8 + tig + 4];
            const int ktg = chunk * 8 + kk2;
            #pragma unroll
            for (int nn = 0; nn < 4; nn++) {
                uint2 bb = *(const uint2*)(vfrag + (ktg * 4 + nn) * 64 + lane * 2);
                mma_tf32(av[nn][0], av[nn][1], av[nn][2], av[nn][3],
                         a0, a1, a2, a3, bb.x, bb.y);
            }
        }
        __syncwarp();
    }

    sumA += __shfl_xor_sync(0xffffffffu, sumA, 1);
    sumA += __shfl_xor_sync(0xffffffffu, sumA, 2);
    sumB += __shfl_xor_sync(0xffffffffu, sumB, 1);
    sumB += __shfl_xor_sync(0xffffffffu, sumB, 2);
    const float invA = 1.0f / sumA;
    const float invB = 1.0f / sumB;

    #pragma unroll
    for (int nn = 0; nn < 4; nn++) {
        const int d = nn * 8 + 2 * tig;
        if (vA) {
            float2 o = make_float2(av[nn][0] * invA, av[nn][1] * invA);
            *(float2*)(g_ao + ((size_t)b * N_TOK + iA) * DIM + h * HD + d) = o;
        }
        if (vB) {
            float2 o = make_float2(av[nn][2] * invB, av[nn][3] * invB);
            *(float2*)(g_ao + ((size_t)b * N_TOK + iB) * DIM + h * HD + d) = o;
        }
    }
}

// ---------------- kernel 3: output projection via tf32 mma -----------------
__global__ __launch_bounds__(256, 2)
void proj_kernel(const float* __restrict__ w,
                 const float* __restrict__ bias,
                 float* __restrict__ out) {
    extern __shared__ float smf[];
    float*    xs    = smf;                       // [128][100]
    unsigned* wfrag = (unsigned*)(smf + 12800);  // [12*12][64]
    float*    bs    = smf + 12800 + 9216;        // [96]
    const int tid = threadIdx.x;
    const int m0  = blockIdx.x * 128;

    for (int idx = tid; idx < 12 * 12 * 32; idx += 256) {
        int t = idx >> 5, l = idx & 31;
        int nt = t / 12, kk = t - nt * 12;
        int gl = l >> 2, tl = l & 3;
        int c  = nt * 8 + gl;
        int k0 = kk * 8 + tl;
        wfrag[t * 64 + l * 2]     = f2tf(w[c * 96 + k0]);
        wfrag[t * 64 + l * 2 + 1] = f2tf(w[c * 96 + k0 + 4]);
    }
    if (tid < 96) bs[tid] = bias[tid];
    for (int idx = tid; idx < 128 * 96; idx += 256) {
        int r = idx / 96, c = idx - r * 96;
        xs[r * 100 + c] = g_ao[(size_t)m0 * 96 + idx];
    }
    __syncthreads();

    const int wp   = tid >> 5;
    const int lane = tid & 31;
    const int g    = lane >> 2;
    const int tig  = lane & 3;

    float acc[12][4];
    #pragma unroll
    for (int nt = 0; nt < 12; nt++)
        #pragma unroll
        for (int e = 0; e < 4; e++) acc[nt][e] = 0.f;

    const float* xrA = xs + (wp * 16 + g) * 100;
    const float* xrB = xrA + 8 * 100;
    #pragma unroll
    for (int kk = 0; kk < 12; kk++) {
        unsigned a0 = f2tf(xrA[kk * 8 + tig]);
        unsigned a1 = f2tf(xrB[kk * 8 + tig]);
        unsigned a2 = f2tf(xrA[kk * 8 + tig + 4]);
        unsigned a3 = f2tf(xrB[kk * 8 + tig + 4]);
        #pragma unroll
        for (int nt = 0; nt < 12; nt++) {
            uint2 bb = *(const uint2*)(wfrag + (nt * 12 + kk) * 64 + lane * 2);
            mma_tf32(acc[nt][0], acc[nt][1], acc[nt][2], acc[nt][3],
                     a0, a1, a2, a3, bb.x, bb.y);
        }
    }

    const size_t mA = m0 + wp * 16 + g;
    const size_t mB = mA + 8;
    #pragma unroll
    for (int nt = 0; nt < 12; nt++) {
        int c0 = nt * 8 + 2 * tig;
        float bb0 = bs[c0], bb1 = bs[c0 + 1];
        *(float2*)(out + mA * 96 + c0) = make_float2(acc[nt][0] + bb0, acc[nt][1] + bb1);
        *(float2*)(out + mB * 96 + c0) = make_float2(acc[nt][2] + bb0, acc[nt][3] + bb1);
    }
}

// ---------------- launch ---------------------------------------------------
extern "C" void kernel_launch(void* const* d_in, const int* in_sizes, int n_in,
                              void* d_out, int out_size) {
    const float* x      = (const float*)d_in[0];
    const float* mask   = (const float*)d_in[1];
    const float* qkv_w  = (const float*)d_in[2];
    const float* qkv_b  = (const float*)d_in[3];
    const float* proj_w = (const float*)d_in[4];
    const float* proj_b = (const float*)d_in[5];
    const float* rpb    = (const float*)d_in[6];
    const int*   relidx = (const int*)d_in[7];
    float* out = (float*)d_out;

    const int smem_attn = (11008 + 11008 + 22 * 16 * 68) * 4;   // 183,808 B
    const int smem_gemm = (12800 + 9216 + 96) * 4;              //  88,448 B
    cudaFuncSetAttribute(attn_kernel, cudaFuncAttributeMaxDynamicSharedMemorySize, smem_attn);
    cudaFuncSetAttribute(qkv_kernel,  cudaFuncAttributeMaxDynamicSharedMemorySize, smem_gemm);
    cudaFuncSetAttribute(proj_kernel, cudaFuncAttributeMaxDynamicSharedMemorySize, smem_gemm);

    cb_kernel  <<<dim3(N_TOK, NW * HEADS), 352>>>(mask, rpb, relidx);
    qkv_kernel <<<dim3(1372, 3), 256, smem_gemm>>>(x, qkv_w, qkv_b);
    attn_kernel<<<B_TOT * HEADS, 704, smem_attn>>>();
    proj_kernel<<<1372, 256, smem_gemm>>>(proj_w, proj_b, out);
    (void)in_sizes; (void)n_in; (void)out_size;
}

// round 6
// speedup vs baseline: 2.1109x; 1.0859x over previous
#include <cuda_runtime.h>
#include <math.h>

#define B_TOT 512
#define N_TOK 343
#define DIM   96
#define HEADS 3
#define HD    32
#define NW    64
#define CB_STRIDE 344
#define CB_SLICE  (N_TOK * CB_STRIDE)   // 117992

// ---------------- scratch (device globals: no allocation allowed) ----------
__device__ float g_q [(size_t)B_TOT * HEADS * N_TOK * HD];   // [B][H][N][hd], pre-scaled
__device__ float g_k [(size_t)B_TOT * HEADS * N_TOK * HD];
__device__ float g_v [(size_t)B_TOT * HEADS * N_TOK * HD];
__device__ float g_ao[(size_t)B_TOT * N_TOK * DIM];          // [B][N][H*hd]
__device__ float g_cb[(size_t)NW * HEADS * CB_SLICE + 64];   // mask+bias, stride-344 rows

// ---------------- helpers --------------------------------------------------
__device__ __forceinline__ float fast_exp(float x) {
    float y = x * 1.4426950408889634f;        // log2(e)
    y = fmaxf(y, -87.0f);
    float t = y + 12582912.0f;                // round-to-nearest magic (1.5*2^23)
    float f = y - (t - 12582912.0f);          // f in [-0.5, 0.5]
    float p = 1.3333558146428443e-3f;
    p = fmaf(p, f, 9.618129107628477e-3f);
    p = fmaf(p, f, 5.550410866482158e-2f);
    p = fmaf(p, f, 2.402265069591007e-1f);
    p = fmaf(p, f, 6.931471805599453e-1f);
    p = fmaf(p, f, 1.0f);
    return __int_as_float(__float_as_int(p) + (__float_as_int(t) << 23));
}

__device__ __forceinline__ unsigned f2tf(float x) {
    unsigned r;
    asm("cvt.rna.tf32.f32 %0, %1;" : "=r"(r) : "f"(x));
    return r;
}

__device__ __forceinline__ void mma_tf32(float& c0, float& c1, float& c2, float& c3,
                                         unsigned a0, unsigned a1, unsigned a2, unsigned a3,
                                         unsigned b0, unsigned b1) {
    asm volatile("mma.sync.aligned.m16n8k8.row.col.f32.tf32.tf32.f32 "
                 "{%0,%1,%2,%3}, {%4,%5,%6,%7}, {%8,%9}, {%0,%1,%2,%3};"
                 : "+f"(c0), "+f"(c1), "+f"(c2), "+f"(c3)
                 : "r"(a0), "r"(a1), "r"(a2), "r"(a3), "r"(b0), "r"(b1));
}

// ---------------- kernel 0: combined bias table (stride 344) ---------------
__global__ __launch_bounds__(352)
void cb_kernel(const float* __restrict__ mask,
               const float* __restrict__ rpb,
               const int*   __restrict__ relidx) {
    const int i  = blockIdx.x;
    const int wh = blockIdx.y;
    const int w  = wh / HEADS;
    const int h  = wh - w * HEADS;
    const int j  = threadIdx.x;
    if (j < N_TOK) {
        int rel = relidx[i * N_TOK + j];
        g_cb[(size_t)wh * CB_SLICE + i * CB_STRIDE + j] =
            mask[(size_t)w * N_TOK * N_TOK + i * N_TOK + j] + rpb[rel * HEADS + h];
    }
}

// ---------------- kernel 1: QKV GEMM via tf32 mma, 3 thirds per CTA --------
// CTA: 128 tokens x (96 cols x 3 thirds looped). X staged once (read 1x from
// DRAM); W re-staged per third. A-frag LDS conflict-free (stride 100).
__global__ __launch_bounds__(256, 2)
void qkv_kernel(const float* __restrict__ x,
                const float* __restrict__ w,
                const float* __restrict__ bias) {
    extern __shared__ float smf[];
    float*    xs    = smf;                       // [128][100]  51200B
    unsigned* wfrag = (unsigned*)(smf + 12800);  // [12*12][64] 36864B
    float*    bs    = smf + 12800 + 9216;        // [96]
    const int tid = threadIdx.x;
    const int m0  = blockIdx.x * 128;

    for (int idx = tid; idx < 128 * 96; idx += 256) {
        int r = idx / 96, c = idx - r * 96;
        xs[r * 100 + c] = x[(size_t)m0 * 96 + idx];
    }

    const int wp   = tid >> 5;
    const int lane = tid & 31;
    const int g    = lane >> 2;
    const int tig  = lane & 3;
    const float qscale = 0.17677669529663687f;

    for (int third = 0; third < 3; third++) {
        __syncthreads();   // xs ready (iter 0) / prior compute done before wfrag overwrite
        for (int idx = tid; idx < 12 * 12 * 32; idx += 256) {
            int t = idx >> 5, l = idx & 31;
            int nt = t / 12, kk = t - nt * 12;
            int gl = l >> 2, tl = l & 3;
            int c  = third * 96 + nt * 8 + gl;
            int k0 = kk * 8 + tl;
            wfrag[t * 64 + l * 2]     = f2tf(w[c * 96 + k0]);
            wfrag[t * 64 + l * 2 + 1] = f2tf(w[c * 96 + k0 + 4]);
        }
        if (tid < 96) bs[tid] = bias[third * 96 + tid];
        __syncthreads();

        float acc[12][4];
        #pragma unroll
        for (int nt = 0; nt < 12; nt++)
            #pragma unroll
            for (int e = 0; e < 4; e++) acc[nt][e] = 0.f;

        const float* xrA = xs + (wp * 16 + g) * 100;
        const float* xrB = xrA + 8 * 100;
        #pragma unroll
        for (int kk = 0; kk < 12; kk++) {
            unsigned a0 = f2tf(xrA[kk * 8 + tig]);
            unsigned a1 = f2tf(xrB[kk * 8 + tig]);
            unsigned a2 = f2tf(xrA[kk * 8 + tig + 4]);
            unsigned a3 = f2tf(xrB[kk * 8 + tig + 4]);
            #pragma unroll
            for (int nt = 0; nt < 12; nt++) {
                uint2 bb = *(const uint2*)(wfrag + (nt * 12 + kk) * 64 + lane * 2);
                mma_tf32(acc[nt][0], acc[nt][1], acc[nt][2], acc[nt][3],
                         a0, a1, a2, a3, bb.x, bb.y);
            }
        }

        const int mA = m0 + wp * 16 + g;
        const int mB = mA + 8;
        const int bA = mA / N_TOK, nA = mA - bA * N_TOK;
        const int bB = mB / N_TOK, nB = mB - bB * N_TOK;
        #pragma unroll
        for (int nt = 0; nt < 12; nt++) {
            int c0 = nt * 8 + 2 * tig;
            int hh = c0 >> 5, d = c0 & 31;
            float bb0 = bs[c0], bb1 = bs[c0 + 1];
            float2 vA = make_float2(acc[nt][0] + bb0, acc[nt][1] + bb1);
            float2 vB = make_float2(acc[nt][2] + bb0, acc[nt][3] + bb1);
            size_t offA = (((size_t)(bA * HEADS + hh)) * N_TOK + nA) * HD + d;
            size_t offB = (((size_t)(bB * HEADS + hh)) * N_TOK + nB) * HD + d;
            if (third == 0) {
                vA.x *= qscale; vA.y *= qscale; vB.x *= qscale; vB.y *= qscale;
                *(float2*)(g_q + offA) = vA; *(float2*)(g_q + offB) = vB;
            } else if (third == 1) {
                *(float2*)(g_k + offA) = vA; *(float2*)(g_k + offB) = vB;
            } else {
                *(float2*)(g_v + offA) = vA; *(float2*)(g_v + offB) = vB;
            }
        }
    }
}

// ---------------- kernel 2: fused attention, register-resident P -----------
// Per score tile: QK mma -> bias+exp -> quad-shuffle reshape (C-frag -> A-frag,
// fixed permutation inside each thread quad) -> AV mma. No smem P buffer, no
// barriers after init. Grid ordered so 8 CTAs sharing a cb slice are adjacent.
__global__ __launch_bounds__(704, 1)
void attn_kernel() {
    extern __shared__ unsigned smu[];
    unsigned* kfrag = smu;               // [43*4][64] : 11008
    unsigned* vfrag = smu + 11008;       // [43*4][64] : 11008

    const int bid  = blockIdx.x;
    const int wh   = bid >> 3;                 // window*3 + h
    const int rep  = bid & 7;
    const int win  = wh / HEADS;
    const int h    = wh - win * HEADS;
    const int b    = rep * NW + win;
    const int tid  = threadIdx.x;
    const int lane = tid & 31;
    const int w    = tid >> 5;           // 0..21
    const int g    = lane >> 2;          // 0..7
    const int tig  = lane & 3;           // 0..3

    const size_t bh_off = ((size_t)(b * HEADS + h)) * N_TOK * HD;
    const float* kg = g_k + bh_off;
    const float* vg = g_v + bh_off;
    const float* qg = g_q + bh_off;
    const float* cbp = g_cb + (size_t)wh * CB_SLICE;

    // ---- build K B-fragments ----
    for (int idx = tid; idx < 43 * 4 * 32; idx += 704) {
        int tile = idx >> 5, l = idx & 31;
        int nt = tile >> 2, kk = tile & 3;
        int gl = l >> 2, tl = l & 3;
        int n = nt * 8 + gl;
        int d0 = kk * 8 + tl;
        float v0 = (n < N_TOK) ? kg[n * 32 + d0]     : 0.f;
        float v1 = (n < N_TOK) ? kg[n * 32 + d0 + 4] : 0.f;
        kfrag[tile * 64 + l * 2]     = f2tf(v0);
        kfrag[tile * 64 + l * 2 + 1] = f2tf(v1);
    }
    // ---- build V B-fragments ----
    for (int idx = tid; idx < 43 * 4 * 32; idx += 704) {
        int tile = idx >> 5, l = idx & 31;
        int kt = tile >> 2, nn = tile & 3;
        int gl = l >> 2, tl = l & 3;
        int k0 = kt * 8;
        float v0 = (k0 + tl     < N_TOK) ? vg[(k0 + tl)     * 32 + nn * 8 + gl] : 0.f;
        float v1 = (k0 + tl + 4 < N_TOK) ? vg[(k0 + tl + 4) * 32 + nn * 8 + gl] : 0.f;
        vfrag[tile * 64 + l * 2]     = f2tf(v0);
        vfrag[tile * 64 + l * 2 + 1] = f2tf(v1);
    }
    __syncthreads();

    const int i0 = w * 16;
    const int iA = i0 + g, iB = i0 + g + 8;
    const bool vA = (iA < N_TOK), vB = (iB < N_TOK);

    unsigned qa[4][4];
    #pragma unroll
    for (int kk = 0; kk < 4; kk++) {
        int d0 = kk * 8 + tig;
        qa[kk][0] = vA ? f2tf(qg[iA * 32 + d0])     : 0u;
        qa[kk][1] = vB ? f2tf(qg[iB * 32 + d0])     : 0u;
        qa[kk][2] = vA ? f2tf(qg[iA * 32 + d0 + 4]) : 0u;
        qa[kk][3] = vB ? f2tf(qg[iB * 32 + d0 + 4]) : 0u;
    }

    float av[4][4];
    #pragma unroll
    for (int nn = 0; nn < 4; nn++)
        #pragma unroll
        for (int e = 0; e < 4; e++) av[nn][e] = 0.f;

    float sumA = 0.f, sumB = 0.f;
    const float* cbA = cbp + (size_t)iA * CB_STRIDE;
    const float* cbB = cbp + (size_t)iB * CB_STRIDE;
    const int srcq0 = (lane & ~3) | (tig >> 1);
    const int srcq1 = srcq0 + 2;
    const bool oddt = tig & 1;

    for (int ntg = 0; ntg < 43; ntg++) {
        const int j0 = ntg * 8 + 2 * tig;

        float cb00, cb01, cb10, cb11;
        if (vA && j0 < N_TOK) {
            float2 t = *(const float2*)(cbA + j0);
            cb00 = t.x; cb01 = t.y;
        } else { cb00 = cb01 = -1e30f; }
        if (vB && j0 < N_TOK) {
            float2 t = *(const float2*)(cbB + j0);
            cb10 = t.x; cb11 = t.y;
        } else { cb10 = cb11 = -1e30f; }
        if (j0 + 1 >= N_TOK) { cb01 = -1e30f; cb11 = -1e30f; }

        float c0 = 0.f, c1 = 0.f, c2 = 0.f, c3 = 0.f;
        #pragma unroll
        for (int kk = 0; kk < 4; kk++) {
            uint2 bb = *(const uint2*)(kfrag + (ntg * 4 + kk) * 64 + lane * 2);
            mma_tf32(c0, c1, c2, c3, qa[kk][0], qa[kk][1], qa[kk][2], qa[kk][3],
                     bb.x, bb.y);
        }

        float p0 = fast_exp(c0 + cb00);
        float p1 = fast_exp(c1 + cb01);
        float p2 = fast_exp(c2 + cb10);
        float p3 = fast_exp(c3 + cb11);
        sumA += p0 + p1;
        sumB += p2 + p3;

        // reshape C-frag (cols 2tig,2tig+1) -> A-frag (cols tig,tig+4) in regs
        unsigned t0 = f2tf(p0), t1 = f2tf(p1), t2 = f2tf(p2), t3 = f2tf(p3);
        unsigned u0 = __shfl_sync(0xffffffffu, t0, srcq0);
        unsigned u1 = __shfl_sync(0xffffffffu, t1, srcq0);
        unsigned u2 = __shfl_sync(0xffffffffu, t2, srcq0);
        unsigned u3 = __shfl_sync(0xffffffffu, t3, srcq0);
        unsigned w0 = __shfl_sync(0xffffffffu, t0, srcq1);
        unsigned w1 = __shfl_sync(0xffffffffu, t1, srcq1);
        unsigned w2 = __shfl_sync(0xffffffffu, t2, srcq1);
        unsigned w3 = __shfl_sync(0xffffffffu, t3, srcq1);
        unsigned a0 = oddt ? u1 : u0;    // P[g   ][8ntg+tig]
        unsigned a1 = oddt ? u3 : u2;    // P[g+8 ][8ntg+tig]
        unsigned a2 = oddt ? w1 : w0;    // P[g   ][8ntg+tig+4]
        unsigned a3 = oddt ? w3 : w2;    // P[g+8 ][8ntg+tig+4]

        #pragma unroll
        for (int nn = 0; nn < 4; nn++) {
            uint2 bb = *(const uint2*)(vfrag + (ntg * 4 + nn) * 64 + lane * 2);
            mma_tf32(av[nn][0], av[nn][1], av[nn][2], av[nn][3],
                     a0, a1, a2, a3, bb.x, bb.y);
        }
    }

    sumA += __shfl_xor_sync(0xffffffffu, sumA, 1);
    sumA += __shfl_xor_sync(0xffffffffu, sumA, 2);
    sumB += __shfl_xor_sync(0xffffffffu, sumB, 1);
    sumB += __shfl_xor_sync(0xffffffffu, sumB, 2);
    const float invA = 1.0f / sumA;
    const float invB = 1.0f / sumB;

    #pragma unroll
    for (int nn = 0; nn < 4; nn++) {
        const int d = nn * 8 + 2 * tig;
        if (vA) {
            float2 o = make_float2(av[nn][0] * invA, av[nn][1] * invA);
            *(float2*)(g_ao + ((size_t)b * N_TOK + iA) * DIM + h * HD + d) = o;
        }
        if (vB) {
            float2 o = make_float2(av[nn][2] * invB, av[nn][3] * invB);
            *(float2*)(g_ao + ((size_t)b * N_TOK + iB) * DIM + h * HD + d) = o;
        }
    }
}

// ---------------- kernel 3: output projection via tf32 mma -----------------
__global__ __launch_bounds__(256, 2)
void proj_kernel(const float* __restrict__ w,
                 const float* __restrict__ bias,
                 float* __restrict__ out) {
    extern __shared__ float smf[];
    float*    xs    = smf;                       // [128][100]
    unsigned* wfrag = (unsigned*)(smf + 12800);  // [12*12][64]
    float*    bs    = smf + 12800 + 9216;        // [96]
    const int tid = threadIdx.x;
    const int m0  = blockIdx.x * 128;

    for (int idx = tid; idx < 12 * 12 * 32; idx += 256) {
        int t = idx >> 5, l = idx & 31;
        int nt = t / 12, kk = t - nt * 12;
        int gl = l >> 2, tl = l & 3;
        int c  = nt * 8 + gl;
        int k0 = kk * 8 + tl;
        wfrag[t * 64 + l * 2]     = f2tf(w[c * 96 + k0]);
        wfrag[t * 64 + l * 2 + 1] = f2tf(w[c * 96 + k0 + 4]);
    }
    if (tid < 96) bs[tid] = bias[tid];
    for (int idx = tid; idx < 128 * 96; idx += 256) {
        int r = idx / 96, c = idx - r * 96;
        xs[r * 100 + c] = g_ao[(size_t)m0 * 96 + idx];
    }
    __syncthreads();

    const int wp   = tid >> 5;
    const int lane = tid & 31;
    const int g    = lane >> 2;
    const int tig  = lane & 3;

    float acc[12][4];
    #pragma unroll
    for (int nt = 0; nt < 12; nt++)
        #pragma unroll
        for (int e = 0; e < 4; e++) acc[nt][e] = 0.f;

    const float* xrA = xs + (wp * 16 + g) * 100;
    const float* xrB = xrA + 8 * 100;
    #pragma unroll
    for (int kk = 0; kk < 12; kk++) {
        unsigned a0 = f2tf(xrA[kk * 8 + tig]);
        unsigned a1 = f2tf(xrB[kk * 8 + tig]);
        unsigned a2 = f2tf(xrA[kk * 8 + tig + 4]);
        unsigned a3 = f2tf(xrB[kk * 8 + tig + 4]);
        #pragma unroll
        for (int nt = 0; nt < 12; nt++) {
            uint2 bb = *(const uint2*)(wfrag + (nt * 12 + kk) * 64 + lane * 2);
            mma_tf32(acc[nt][0], acc[nt][1], acc[nt][2], acc[nt][3],
                     a0, a1, a2, a3, bb.x, bb.y);
        }
    }

    const size_t mA = m0 + wp * 16 + g;
    const size_t mB = mA + 8;
    #pragma unroll
    for (int nt = 0; nt < 12; nt++) {
        int c0 = nt * 8 + 2 * tig;
        float bb0 = bs[c0], bb1 = bs[c0 + 1];
        *(float2*)(out + mA * 96 + c0) = make_float2(acc[nt][0] + bb0, acc[nt][1] + bb1);
        *(float2*)(out + mB * 96 + c0) = make_float2(acc[nt][2] + bb0, acc[nt][3] + bb1);
    }
}

// ---------------- launch ---------------------------------------------------
extern "C" void kernel_launch(void* const* d_in, const int* in_sizes, int n_in,
                              void* d_out, int out_size) {
    const float* x      = (const float*)d_in[0];
    const float* mask   = (const float*)d_in[1];
    const float* qkv_w  = (const float*)d_in[2];
    const float* qkv_b  = (const float*)d_in[3];
    const float* proj_w = (const float*)d_in[4];
    const float* proj_b = (const float*)d_in[5];
    const float* rpb    = (const float*)d_in[6];
    const int*   relidx = (const int*)d_in[7];
    float* out = (float*)d_out;

    const int smem_attn = 22016 * 4;                 //  88,064 B
    const int smem_gemm = (12800 + 9216 + 96) * 4;   //  88,448 B
    cudaFuncSetAttribute(attn_kernel, cudaFuncAttributeMaxDynamicSharedMemorySize, smem_attn);
    cudaFuncSetAttribute(qkv_kernel,  cudaFuncAttributeMaxDynamicSharedMemorySize, smem_gemm);
    cudaFuncSetAttribute(proj_kernel, cudaFuncAttributeMaxDynamicSharedMemorySize, smem_gemm);

    cb_kernel  <<<dim3(N_TOK, NW * HEADS), 352>>>(mask, rpb, relidx);
    qkv_kernel <<<1372, 256, smem_gemm>>>(x, qkv_w, qkv_b);
    attn_kernel<<<B_TOT * HEADS, 704, smem_attn>>>();
    proj_kernel<<<1372, 256, smem_gemm>>>(proj_w, proj_b, out);
    (void)in_sizes; (void)n_in; (void)out_size;
}

// round 7
// speedup vs baseline: 2.2017x; 1.0430x over previous
#include <cuda_runtime.h>
#include <math.h>

#define B_TOT 512
#define N_TOK 343
#define DIM   96
#define HEADS 3
#define HD    32
#define NW    64
#define CB_STRIDE 344
#define CB_SLICE  (N_TOK * CB_STRIDE)   // 117992

// ---------------- scratch (device globals: no allocation allowed) ----------
__device__ float g_q [(size_t)B_TOT * HEADS * N_TOK * HD];   // [B][H][N][hd], pre-scaled
__device__ float g_k [(size_t)B_TOT * HEADS * N_TOK * HD];
__device__ float g_v [(size_t)B_TOT * HEADS * N_TOK * HD];
__device__ float g_ao[(size_t)B_TOT * N_TOK * DIM];          // [B][N][H*hd]
__device__ float g_cb[(size_t)NW * HEADS * CB_SLICE + 64];   // mask+bias, stride-344 rows

// ---------------- helpers --------------------------------------------------
__device__ __forceinline__ float fast_exp(float x) {
    float y = x * 1.4426950408889634f;        // log2(e)
    y = fmaxf(y, -87.0f);
    float t = y + 12582912.0f;                // round-to-nearest magic (1.5*2^23)
    float f = y - (t - 12582912.0f);          // f in [-0.5, 0.5]
    float p = 1.3333558146428443e-3f;
    p = fmaf(p, f, 9.618129107628477e-3f);
    p = fmaf(p, f, 5.550410866482158e-2f);
    p = fmaf(p, f, 2.402265069591007e-1f);
    p = fmaf(p, f, 6.931471805599453e-1f);
    p = fmaf(p, f, 1.0f);
    return __int_as_float(__float_as_int(p) + (__float_as_int(t) << 23));
}

__device__ __forceinline__ unsigned f2tf(float x) {
    unsigned r;
    asm("cvt.rna.tf32.f32 %0, %1;" : "=r"(r) : "f"(x));
    return r;
}

__device__ __forceinline__ void mma_tf32(float& c0, float& c1, float& c2, float& c3,
                                         unsigned a0, unsigned a1, unsigned a2, unsigned a3,
                                         unsigned b0, unsigned b1) {
    asm volatile("mma.sync.aligned.m16n8k8.row.col.f32.tf32.tf32.f32 "
                 "{%0,%1,%2,%3}, {%4,%5,%6,%7}, {%8,%9}, {%0,%1,%2,%3};"
                 : "+f"(c0), "+f"(c1), "+f"(c2), "+f"(c3)
                 : "r"(a0), "r"(a1), "r"(a2), "r"(a3), "r"(b0), "r"(b1));
}

// ---------------- kernel 0: combined bias table (stride 344) ---------------
__global__ __launch_bounds__(352)
void cb_kernel(const float* __restrict__ mask,
               const float* __restrict__ rpb,
               const int*   __restrict__ relidx) {
    const int i  = blockIdx.x;
    const int wh = blockIdx.y;
    const int w  = wh / HEADS;
    const int h  = wh - w * HEADS;
    const int j  = threadIdx.x;
    if (j < N_TOK) {
        int rel = relidx[i * N_TOK + j];
        g_cb[(size_t)wh * CB_SLICE + i * CB_STRIDE + j] =
            mask[(size_t)w * N_TOK * N_TOK + i * N_TOK + j] + rpb[rel * HEADS + h];
    }
}

// ---------------- kernel 1: QKV GEMM, tf32 mma, B-frags in registers -------
// Warp owns 24 cols (3 nt) x all K: 36 B-frags in regs, loaded once per
// third. Streams 4 m16-stripes of its 64-row half. No LDS in mma chain
// except the shared 4-LDS A-frag per kk.
__global__ __launch_bounds__(256, 2)
void qkv_kernel(const float* __restrict__ x,
                const float* __restrict__ w,
                const float* __restrict__ bias) {
    extern __shared__ float smf[];
    float*    xs    = smf;                       // [128][100]  51200B
    unsigned* wfrag = (unsigned*)(smf + 12800);  // [12*12][64] 36864B
    float*    bs    = smf + 12800 + 9216;        // [96]
    const int tid = threadIdx.x;
    const int m0  = blockIdx.x * 128;

    for (int idx = tid; idx < 128 * 96; idx += 256) {
        int r = idx / 96, c = idx - r * 96;
        xs[r * 100 + c] = x[(size_t)m0 * 96 + idx];
    }

    const int wp   = tid >> 5;
    const int lane = tid & 31;
    const int g    = lane >> 2;
    const int tig  = lane & 3;
    const int cg   = wp & 3;        // col group: nt = 3*cg + ntl
    const int mh   = wp >> 2;       // row half: rows [64*mh, 64*mh+64)
    const float qscale = 0.17677669529663687f;

    for (int third = 0; third < 3; third++) {
        __syncthreads();
        for (int idx = tid; idx < 12 * 12 * 32; idx += 256) {
            int t = idx >> 5, l = idx & 31;
            int nt = t / 12, kk = t - nt * 12;
            int gl = l >> 2, tl = l & 3;
            int c  = third * 96 + nt * 8 + gl;
            int k0 = kk * 8 + tl;
            wfrag[t * 64 + l * 2]     = f2tf(w[c * 96 + k0]);
            wfrag[t * 64 + l * 2 + 1] = f2tf(w[c * 96 + k0 + 4]);
        }
        if (tid < 96) bs[tid] = bias[third * 96 + tid];
        __syncthreads();

        // B-frags resident in registers (36 x uint2)
        uint2 breg[12][3];
        #pragma unroll
        for (int kk = 0; kk < 12; kk++)
            #pragma unroll
            for (int ntl = 0; ntl < 3; ntl++)
                breg[kk][ntl] = *(const uint2*)(wfrag + ((3 * cg + ntl) * 12 + kk) * 64 + lane * 2);

        #pragma unroll
        for (int s = 0; s < 4; s++) {
            const float* xrA = xs + (mh * 64 + s * 16 + g) * 100;
            const float* xrB = xrA + 800;

            float acc[3][4];
            #pragma unroll
            for (int ntl = 0; ntl < 3; ntl++)
                #pragma unroll
                for (int e = 0; e < 4; e++) acc[ntl][e] = 0.f;

            #pragma unroll
            for (int kk = 0; kk < 12; kk++) {
                unsigned a0 = f2tf(xrA[kk * 8 + tig]);
                unsigned a1 = f2tf(xrB[kk * 8 + tig]);
                unsigned a2 = f2tf(xrA[kk * 8 + tig + 4]);
                unsigned a3 = f2tf(xrB[kk * 8 + tig + 4]);
                #pragma unroll
                for (int ntl = 0; ntl < 3; ntl++)
                    mma_tf32(acc[ntl][0], acc[ntl][1], acc[ntl][2], acc[ntl][3],
                             a0, a1, a2, a3, breg[kk][ntl].x, breg[kk][ntl].y);
            }

            const int mA = m0 + mh * 64 + s * 16 + g;
            const int mB = mA + 8;
            const int bA = mA / N_TOK, nA = mA - bA * N_TOK;
            const int bB = mB / N_TOK, nB = mB - bB * N_TOK;
            #pragma unroll
            for (int ntl = 0; ntl < 3; ntl++) {
                int c0 = (3 * cg + ntl) * 8 + 2 * tig;
                int hh = c0 >> 5, d = c0 & 31;
                float bb0 = bs[c0], bb1 = bs[c0 + 1];
                float2 vA = make_float2(acc[ntl][0] + bb0, acc[ntl][1] + bb1);
                float2 vB = make_float2(acc[ntl][2] + bb0, acc[ntl][3] + bb1);
                size_t offA = (((size_t)(bA * HEADS + hh)) * N_TOK + nA) * HD + d;
                size_t offB = (((size_t)(bB * HEADS + hh)) * N_TOK + nB) * HD + d;
                if (third == 0) {
                    vA.x *= qscale; vA.y *= qscale; vB.x *= qscale; vB.y *= qscale;
                    *(float2*)(g_q + offA) = vA; *(float2*)(g_q + offB) = vB;
                } else if (third == 1) {
                    *(float2*)(g_k + offA) = vA; *(float2*)(g_k + offB) = vB;
                } else {
                    *(float2*)(g_v + offA) = vA; *(float2*)(g_v + offB) = vB;
                }
            }
        }
    }
}

// ---------------- kernel 2: fused attention, paired-tile ILP ---------------
// 44 j-tiles (tile 43 fully poisoned -> p=0, no contribution). Tiles
// processed in pairs: two independent QK chains + exp + shfl + AV per
// iteration to cover mma/shfl latency. Register-resident P throughout.
__global__ __launch_bounds__(704, 1)
void attn_kernel() {
    extern __shared__ unsigned smu[];
    unsigned* kfrag = smu;               // [44*4][64] : 11264
    unsigned* vfrag = smu + 11264;       // [44*4][64] : 11264

    const int bid  = blockIdx.x;
    const int wh   = bid >> 3;                 // window*3 + h
    const int rep  = bid & 7;
    const int win  = wh / HEADS;
    const int h    = wh - win * HEADS;
    const int b    = rep * NW + win;
    const int tid  = threadIdx.x;
    const int lane = tid & 31;
    const int w    = tid >> 5;           // 0..21
    const int g    = lane >> 2;          // 0..7
    const int tig  = lane & 3;           // 0..3

    const size_t bh_off = ((size_t)(b * HEADS + h)) * N_TOK * HD;
    const float* kg = g_k + bh_off;
    const float* vg = g_v + bh_off;
    const float* qg = g_q + bh_off;
    const float* cbp = g_cb + (size_t)wh * CB_SLICE;

    // ---- build K B-fragments (44 tiles, padded rows zero) ----
    for (int idx = tid; idx < 44 * 4 * 32; idx += 704) {
        int tile = idx >> 5, l = idx & 31;
        int nt = tile >> 2, kk = tile & 3;
        int gl = l >> 2, tl = l & 3;
        int n = nt * 8 + gl;
        int d0 = kk * 8 + tl;
        float v0 = (n < N_TOK) ? kg[n * 32 + d0]     : 0.f;
        float v1 = (n < N_TOK) ? kg[n * 32 + d0 + 4] : 0.f;
        kfrag[tile * 64 + l * 2]     = f2tf(v0);
        kfrag[tile * 64 + l * 2 + 1] = f2tf(v1);
    }
    // ---- build V B-fragments ----
    for (int idx = tid; idx < 44 * 4 * 32; idx += 704) {
        int tile = idx >> 5, l = idx & 31;
        int kt = tile >> 2, nn = tile & 3;
        int gl = l >> 2, tl = l & 3;
        int k0 = kt * 8;
        float v0 = (k0 + tl     < N_TOK) ? vg[(k0 + tl)     * 32 + nn * 8 + gl] : 0.f;
        float v1 = (k0 + tl + 4 < N_TOK) ? vg[(k0 + tl + 4) * 32 + nn * 8 + gl] : 0.f;
        vfrag[tile * 64 + l * 2]     = f2tf(v0);
        vfrag[tile * 64 + l * 2 + 1] = f2tf(v1);
    }
    __syncthreads();

    const int i0 = w * 16;
    const int iA = i0 + g, iB = i0 + g + 8;
    const bool vA = (iA < N_TOK), vB = (iB < N_TOK);

    unsigned qa[4][4];
    #pragma unroll
    for (int kk = 0; kk < 4; kk++) {
        int d0 = kk * 8 + tig;
        qa[kk][0] = vA ? f2tf(qg[iA * 32 + d0])     : 0u;
        qa[kk][1] = vB ? f2tf(qg[iB * 32 + d0])     : 0u;
        qa[kk][2] = vA ? f2tf(qg[iA * 32 + d0 + 4]) : 0u;
        qa[kk][3] = vB ? f2tf(qg[iB * 32 + d0 + 4]) : 0u;
    }

    float av[4][4];
    #pragma unroll
    for (int nn = 0; nn < 4; nn++)
        #pragma unroll
        for (int e = 0; e < 4; e++) av[nn][e] = 0.f;

    float sumA = 0.f, sumB = 0.f;
    const float* cbA = cbp + (size_t)iA * CB_STRIDE;
    const float* cbB = cbp + (size_t)iB * CB_STRIDE;
    const int srcq0 = (lane & ~3) | (tig >> 1);
    const int srcq1 = srcq0 + 2;
    const bool oddt = tig & 1;

    for (int tp = 0; tp < 22; tp++) {
        // ---- stage 1: bias loads for both tiles ----
        float cb[2][4];
        #pragma unroll
        for (int tt = 0; tt < 2; tt++) {
            const int j0 = (2 * tp + tt) * 8 + 2 * tig;
            float c00, c01, c10, c11;
            if (vA && j0 < N_TOK) {
                float2 t = *(const float2*)(cbA + j0);
                c00 = t.x; c01 = t.y;
            } else { c00 = c01 = -1e30f; }
            if (vB && j0 < N_TOK) {
                float2 t = *(const float2*)(cbB + j0);
                c10 = t.x; c11 = t.y;
            } else { c10 = c11 = -1e30f; }
            if (j0 + 1 >= N_TOK) { c01 = -1e30f; c11 = -1e30f; }
            cb[tt][0] = c00; cb[tt][1] = c01; cb[tt][2] = c10; cb[tt][3] = c11;
        }

        // ---- stage 2: QK mma, two independent chains ----
        float c[2][4];
        #pragma unroll
        for (int tt = 0; tt < 2; tt++) {
            c[tt][0] = c[tt][1] = c[tt][2] = c[tt][3] = 0.f;
            const int ntg = 2 * tp + tt;
            #pragma unroll
            for (int kk = 0; kk < 4; kk++) {
                uint2 bb = *(const uint2*)(kfrag + (ntg * 4 + kk) * 64 + lane * 2);
                mma_tf32(c[tt][0], c[tt][1], c[tt][2], c[tt][3],
                         qa[kk][0], qa[kk][1], qa[kk][2], qa[kk][3], bb.x, bb.y);
            }
        }

        // ---- stage 3: exp (both tiles) ----
        float p[2][4];
        #pragma unroll
        for (int tt = 0; tt < 2; tt++) {
            p[tt][0] = fast_exp(c[tt][0] + cb[tt][0]);
            p[tt][1] = fast_exp(c[tt][1] + cb[tt][1]);
            p[tt][2] = fast_exp(c[tt][2] + cb[tt][2]);
            p[tt][3] = fast_exp(c[tt][3] + cb[tt][3]);
            sumA += p[tt][0] + p[tt][1];
            sumB += p[tt][2] + p[tt][3];
        }

        // ---- stage 4: reshape C-frag -> A-frag (both tiles) ----
        unsigned af[2][4];
        #pragma unroll
        for (int tt = 0; tt < 2; tt++) {
            unsigned t0 = f2tf(p[tt][0]), t1 = f2tf(p[tt][1]);
            unsigned t2 = f2tf(p[tt][2]), t3 = f2tf(p[tt][3]);
            unsigned u0 = __shfl_sync(0xffffffffu, t0, srcq0);
            unsigned u1 = __shfl_sync(0xffffffffu, t1, srcq0);
            unsigned u2 = __shfl_sync(0xffffffffu, t2, srcq0);
            unsigned u3 = __shfl_sync(0xffffffffu, t3, srcq0);
            unsigned w0 = __shfl_sync(0xffffffffu, t0, srcq1);
            unsigned w1 = __shfl_sync(0xffffffffu, t1, srcq1);
            unsigned w2 = __shfl_sync(0xffffffffu, t2, srcq1);
            unsigned w3 = __shfl_sync(0xffffffffu, t3, srcq1);
            af[tt][0] = oddt ? u1 : u0;
            af[tt][1] = oddt ? u3 : u2;
            af[tt][2] = oddt ? w1 : w0;
            af[tt][3] = oddt ? w3 : w2;
        }

        // ---- stage 5: AV mma (both tiles) ----
        #pragma unroll
        for (int tt = 0; tt < 2; tt++) {
            const int ntg = 2 * tp + tt;
            #pragma unroll
            for (int nn = 0; nn < 4; nn++) {
                uint2 bb = *(const uint2*)(vfrag + (ntg * 4 + nn) * 64 + lane * 2);
                mma_tf32(av[nn][0], av[nn][1], av[nn][2], av[nn][3],
                         af[tt][0], af[tt][1], af[tt][2], af[tt][3], bb.x, bb.y);
            }
        }
    }

    sumA += __shfl_xor_sync(0xffffffffu, sumA, 1);
    sumA += __shfl_xor_sync(0xffffffffu, sumA, 2);
    sumB += __shfl_xor_sync(0xffffffffu, sumB, 1);
    sumB += __shfl_xor_sync(0xffffffffu, sumB, 2);
    const float invA = 1.0f / sumA;
    const float invB = 1.0f / sumB;

    #pragma unroll
    for (int nn = 0; nn < 4; nn++) {
        const int d = nn * 8 + 2 * tig;
        if (vA) {
            float2 o = make_float2(av[nn][0] * invA, av[nn][1] * invA);
            *(float2*)(g_ao + ((size_t)b * N_TOK + iA) * DIM + h * HD + d) = o;
        }
        if (vB) {
            float2 o = make_float2(av[nn][2] * invB, av[nn][3] * invB);
            *(float2*)(g_ao + ((size_t)b * N_TOK + iB) * DIM + h * HD + d) = o;
        }
    }
}

// ---------------- kernel 3: output projection, B-frags in registers --------
__global__ __launch_bounds__(256, 2)
void proj_kernel(const float* __restrict__ w,
                 const float* __restrict__ bias,
                 float* __restrict__ out) {
    extern __shared__ float smf[];
    float*    xs    = smf;                       // [128][100]
    unsigned* wfrag = (unsigned*)(smf + 12800);  // [12*12][64]
    float*    bs    = smf + 12800 + 9216;        // [96]
    const int tid = threadIdx.x;
    const int m0  = blockIdx.x * 128;

    for (int idx = tid; idx < 12 * 12 * 32; idx += 256) {
        int t = idx >> 5, l = idx & 31;
        int nt = t / 12, kk = t - nt * 12;
        int gl = l >> 2, tl = l & 3;
        int c  = nt * 8 + gl;
        int k0 = kk * 8 + tl;
        wfrag[t * 64 + l * 2]     = f2tf(w[c * 96 + k0]);
        wfrag[t * 64 + l * 2 + 1] = f2tf(w[c * 96 + k0 + 4]);
    }
    if (tid < 96) bs[tid] = bias[tid];
    for (int idx = tid; idx < 128 * 96; idx += 256) {
        int r = idx / 96, c = idx - r * 96;
        xs[r * 100 + c] = g_ao[(size_t)m0 * 96 + idx];
    }
    __syncthreads();

    const int wp   = tid >> 5;
    const int lane = tid & 31;
    const int g    = lane >> 2;
    const int tig  = lane & 3;
    const int cg   = wp & 3;
    const int mh   = wp >> 2;

    uint2 breg[12][3];
    #pragma unroll
    for (int kk = 0; kk < 12; kk++)
        #pragma unroll
        for (int ntl = 0; ntl < 3; ntl++)
            breg[kk][ntl] = *(const uint2*)(wfrag + ((3 * cg + ntl) * 12 + kk) * 64 + lane * 2);

    #pragma unroll
    for (int s = 0; s < 4; s++) {
        const float* xrA = xs + (mh * 64 + s * 16 + g) * 100;
        const float* xrB = xrA + 800;

        float acc[3][4];
        #pragma unroll
        for (int ntl = 0; ntl < 3; ntl++)
            #pragma unroll
            for (int e = 0; e < 4; e++) acc[ntl][e] = 0.f;

        #pragma unroll
        for (int kk = 0; kk < 12; kk++) {
            unsigned a0 = f2tf(xrA[kk * 8 + tig]);
            unsigned a1 = f2tf(xrB[kk * 8 + tig]);
            unsigned a2 = f2tf(xrA[kk * 8 + tig + 4]);
            unsigned a3 = f2tf(xrB[kk * 8 + tig + 4]);
            #pragma unroll
            for (int ntl = 0; ntl < 3; ntl++)
                mma_tf32(acc[ntl][0], acc[ntl][1], acc[ntl][2], acc[ntl][3],
                         a0, a1, a2, a3, breg[kk][ntl].x, breg[kk][ntl].y);
        }

        const size_t mA = m0 + mh * 64 + s * 16 + g;
        const size_t mB = mA + 8;
        #pragma unroll
        for (int ntl = 0; ntl < 3; ntl++) {
            int c0 = (3 * cg + ntl) * 8 + 2 * tig;
            float bb0 = bs[c0], bb1 = bs[c0 + 1];
            *(float2*)(out + mA * 96 + c0) = make_float2(acc[ntl][0] + bb0, acc[ntl][1] + bb1);
            *(float2*)(out + mB * 96 + c0) = make_float2(acc[ntl][2] + bb0, acc[ntl][3] + bb1);
        }
    }
}

// ---------------- launch ---------------------------------------------------
extern "C" void kernel_launch(void* const* d_in, const int* in_sizes, int n_in,
                              void* d_out, int out_size) {
    const float* x      = (const float*)d_in[0];
    const float* mask   = (const float*)d_in[1];
    const float* qkv_w  = (const float*)d_in[2];
    const float* qkv_b  = (const float*)d_in[3];
    const float* proj_w = (const float*)d_in[4];
    const float* proj_b = (const float*)d_in[5];
    const float* rpb    = (const float*)d_in[6];
    const int*   relidx = (const int*)d_in[7];
    float* out = (float*)d_out;

    const int smem_attn = (11264 + 11264) * 4;       //  90,112 B
    const int smem_gemm = (12800 + 9216 + 96) * 4;   //  88,448 B
    cudaFuncSetAttribute(attn_kernel, cudaFuncAttributeMaxDynamicSharedMemorySize, smem_attn);
    cudaFuncSetAttribute(qkv_kernel,  cudaFuncAttributeMaxDynamicSharedMemorySize, smem_gemm);
    cudaFuncSetAttribute(proj_kernel, cudaFuncAttributeMaxDynamicSharedMemorySize, smem_gemm);

    cb_kernel  <<<dim3(N_TOK, NW * HEADS), 352>>>(mask, rpb, relidx);
    qkv_kernel <<<1372, 256, smem_gemm>>>(x, qkv_w, qkv_b);
    attn_kernel<<<B_TOT * HEADS, 704, smem_attn>>>();
    proj_kernel<<<1372, 256, smem_gemm>>>(proj_w, proj_b, out);
    (void)in_sizes; (void)n_in; (void)out_size;
}